// round 1
// baseline (speedup 1.0000x reference)
#include <cuda_runtime.h>
#include <math.h>

#define N_NODES   100000
#define N_EDGES   1600000
#define IN_F      50
#define AGG_STRIDE 52     // pad 50 -> 52 floats (208B, 16B-aligned rows)
#define HID       64
#define NC        41
#define OSTRIDE   48      // pad 41 -> 48 floats (192B, 16B-aligned rows)

// Scratch (no cudaMalloc allowed)
__device__ __align__(16) float g_agg1[N_NODES * AGG_STRIDE]; // 20.8 MB
__device__ __align__(16) float g_h1[N_NODES * HID];          // 25.6 MB
__device__ __align__(16) float g_z[N_NODES * OSTRIDE];       // 19.2 MB
__device__ __align__(16) float g_o[N_NODES * OSTRIDE];       // 19.2 MB

// ---------------------------------------------------------------------------
// red.global.add.v4.f32 wrapper (REDG, no return value; sm_90+)
// ---------------------------------------------------------------------------
__device__ __forceinline__ void red_add_v4(float* p, float4 v) {
    asm volatile("red.global.add.v4.f32 [%0], {%1, %2, %3, %4};"
                 :: "l"(p), "f"(v.x), "f"(v.y), "f"(v.z), "f"(v.w)
                 : "memory");
}

// ---------------------------------------------------------------------------
// Zero agg1 scratch (must be re-zeroed every replay)
// ---------------------------------------------------------------------------
__global__ void k_zero_agg1() {
    const int total = N_NODES * AGG_STRIDE / 4; // 1.3M float4
    float4* p = reinterpret_cast<float4*>(g_agg1);
    for (int i = blockIdx.x * blockDim.x + threadIdx.x; i < total;
         i += gridDim.x * blockDim.x)
        p[i] = make_float4(0.f, 0.f, 0.f, 0.f);
}

// ---------------------------------------------------------------------------
// Layer-1 scatter: agg1[dst] += x[src]  (half-warp per edge, float4 atomics)
// x rows are 200B (only 8B aligned) -> read as float2 pairs, pack to float4.
// ---------------------------------------------------------------------------
__global__ void k_scatter1(const float* __restrict__ x,
                           const int* __restrict__ src,
                           const int* __restrict__ dst) {
    int t = blockIdx.x * blockDim.x + threadIdx.x;
    int e = t >> 4;
    int lane = t & 15;
    if (e >= N_EDGES) return;
    int s = __ldg(&src[e]);
    int d = __ldg(&dst[e]);
    if (lane < 13) {
        const float2* xr = reinterpret_cast<const float2*>(x + (long)s * IN_F);
        float2 a = __ldg(&xr[2 * lane]);
        float2 b = (2 * lane + 1 < 25) ? __ldg(&xr[2 * lane + 1])
                                       : make_float2(0.f, 0.f);
        red_add_v4(g_agg1 + (long)d * AGG_STRIDE + 4 * lane,
                   make_float4(a.x, a.y, b.x, b.y));
    }
}

// ---------------------------------------------------------------------------
// Dense layer 1: h1 = relu(agg1 @ W1_l + x @ W1_r + b1)
// 16 nodes x 64 cols per block (256 threads); thread owns (node, 4 cols).
// ---------------------------------------------------------------------------
__global__ void k_dense1(const float* __restrict__ x,
                         const float* __restrict__ W1l,
                         const float* __restrict__ W1r,
                         const float* __restrict__ b1) {
    __shared__ __align__(16) float sWl[IN_F * HID];
    __shared__ __align__(16) float sWr[IN_F * HID];
    __shared__ float sA[16 * AGG_STRIDE];
    __shared__ float sX[16 * IN_F];

    int tid = threadIdx.x;             // 256
    int node0 = blockIdx.x * 16;

    for (int i = tid; i < IN_F * HID; i += 256) {
        sWl[i] = W1l[i];
        sWr[i] = W1r[i];
    }
    for (int i = tid; i < 16 * AGG_STRIDE; i += 256)
        sA[i] = g_agg1[(long)node0 * AGG_STRIDE + i];
    for (int i = tid; i < 16 * IN_F; i += 256)
        sX[i] = x[(long)node0 * IN_F + i];
    __syncthreads();

    int jg = tid & 15;                 // column group: cols 4*jg .. 4*jg+3
    int m  = tid >> 4;                 // node within tile
    const float* aRow = &sA[m * AGG_STRIDE];
    const float* xRow = &sX[m * IN_F];

    float4 acc = make_float4(0.f, 0.f, 0.f, 0.f);
#pragma unroll
    for (int k = 0; k < IN_F; k++) {
        float4 wl = *reinterpret_cast<const float4*>(&sWl[k * HID + 4 * jg]);
        float4 wr = *reinterpret_cast<const float4*>(&sWr[k * HID + 4 * jg]);
        float av = aRow[k];
        float xv = xRow[k];
        acc.x += av * wl.x + xv * wr.x;
        acc.y += av * wl.y + xv * wr.y;
        acc.z += av * wl.z + xv * wr.z;
        acc.w += av * wl.w + xv * wr.w;
    }
    float4 bb = *reinterpret_cast<const float4*>(&b1[4 * jg]);
    acc.x = fmaxf(acc.x + bb.x, 0.f);
    acc.y = fmaxf(acc.y + bb.y, 0.f);
    acc.z = fmaxf(acc.z + bb.z, 0.f);
    acc.w = fmaxf(acc.w + bb.w, 0.f);
    *reinterpret_cast<float4*>(&g_h1[(long)(node0 + m) * HID + 4 * jg]) = acc;
}

// ---------------------------------------------------------------------------
// Dense layer 2 pre-aggregation:
//   z = h1 @ W2_l                (aggregated over edges afterward)
//   o = h1 @ W2_r + b2           (self term, scatter2 accumulates into it)
// 16 nodes x 48 cols (41 real, 7 zero-pad) per block; 192 threads.
// ---------------------------------------------------------------------------
__global__ void k_dense2(const float* __restrict__ W2l,
                         const float* __restrict__ W2r,
                         const float* __restrict__ b2) {
    __shared__ __align__(16) float sWl[HID * OSTRIDE];
    __shared__ __align__(16) float sWr[HID * OSTRIDE];
    __shared__ float sH[16 * HID];
    __shared__ __align__(16) float sB[OSTRIDE];

    int tid = threadIdx.x;             // 192
    int node0 = blockIdx.x * 16;

    for (int i = tid; i < HID * OSTRIDE; i += 192) {
        int k = i / OSTRIDE;
        int c = i - k * OSTRIDE;
        float vl = (c < NC) ? W2l[k * NC + c] : 0.f;
        float vr = (c < NC) ? W2r[k * NC + c] : 0.f;
        sWl[i] = vl;
        sWr[i] = vr;
    }
    for (int i = tid; i < 16 * HID; i += 192)
        sH[i] = g_h1[(long)node0 * HID + i];
    if (tid < OSTRIDE)
        sB[tid] = (tid < NC) ? b2[tid] : 0.f;
    __syncthreads();

    int jg = tid % 12;                 // cols 4*jg .. 4*jg+3 (of 48)
    int m  = tid / 12;                 // node within tile (0..15)
    const float* hRow = &sH[m * HID];

    float4 az = make_float4(0.f, 0.f, 0.f, 0.f);
    float4 ao = make_float4(0.f, 0.f, 0.f, 0.f);
#pragma unroll
    for (int k = 0; k < HID; k++) {
        float4 wl = *reinterpret_cast<const float4*>(&sWl[k * OSTRIDE + 4 * jg]);
        float4 wr = *reinterpret_cast<const float4*>(&sWr[k * OSTRIDE + 4 * jg]);
        float h = hRow[k];
        az.x += h * wl.x; az.y += h * wl.y; az.z += h * wl.z; az.w += h * wl.w;
        ao.x += h * wr.x; ao.y += h * wr.y; ao.z += h * wr.z; ao.w += h * wr.w;
    }
    float4 bb = *reinterpret_cast<const float4*>(&sB[4 * jg]);
    ao.x += bb.x; ao.y += bb.y; ao.z += bb.z; ao.w += bb.w;

    long off = (long)(node0 + m) * OSTRIDE + 4 * jg;
    *reinterpret_cast<float4*>(&g_z[off]) = az;
    *reinterpret_cast<float4*>(&g_o[off]) = ao;
}

// ---------------------------------------------------------------------------
// Layer-2 scatter: o[dst] += z[src]  (half-warp per edge, float4 atomics)
// ---------------------------------------------------------------------------
__global__ void k_scatter2(const int* __restrict__ src,
                           const int* __restrict__ dst) {
    int t = blockIdx.x * blockDim.x + threadIdx.x;
    int e = t >> 4;
    int lane = t & 15;
    if (e >= N_EDGES) return;
    int s = __ldg(&src[e]);
    int d = __ldg(&dst[e]);
    if (lane < 12) {
        float4 v = *reinterpret_cast<const float4*>(
            &g_z[(long)s * OSTRIDE + 4 * lane]);
        red_add_v4(&g_o[(long)d * OSTRIDE + 4 * lane], v);
    }
}

// ---------------------------------------------------------------------------
// log_softmax over 41 classes, warp per node, write to packed [N,41] output
// ---------------------------------------------------------------------------
__global__ void k_softmax(float* __restrict__ out) {
    int t = blockIdx.x * blockDim.x + threadIdx.x;
    int n = t >> 5;
    int lane = t & 31;
    if (n >= N_NODES) return;

    const float* row = &g_o[(long)n * OSTRIDE];
    float v0 = row[lane];                                   // cols 0..31
    float v1 = (lane < NC - 32) ? row[32 + lane] : -INFINITY; // cols 32..40

    float mx = fmaxf(v0, v1);
#pragma unroll
    for (int off = 16; off > 0; off >>= 1)
        mx = fmaxf(mx, __shfl_xor_sync(0xFFFFFFFFu, mx, off));

    float sum = expf(v0 - mx) + ((lane < NC - 32) ? expf(v1 - mx) : 0.f);
#pragma unroll
    for (int off = 16; off > 0; off >>= 1)
        sum += __shfl_xor_sync(0xFFFFFFFFu, sum, off);

    float lse = mx + logf(sum);
    out[(long)n * NC + lane] = v0 - lse;
    if (lane < NC - 32)
        out[(long)n * NC + 32 + lane] = v1 - lse;
}

// ---------------------------------------------------------------------------
extern "C" void kernel_launch(void* const* d_in, const int* in_sizes, int n_in,
                              void* d_out, int out_size) {
    const float* x   = (const float*)d_in[0];
    const float* W1l = (const float*)d_in[1];
    const float* W1r = (const float*)d_in[2];
    const float* b1  = (const float*)d_in[3];
    const float* W2l = (const float*)d_in[4];
    const float* W2r = (const float*)d_in[5];
    const float* b2  = (const float*)d_in[6];
    const int*   src = (const int*)d_in[7];
    const int*   dst = (const int*)d_in[8];
    float* out = (float*)d_out;

    (void)in_sizes; (void)n_in; (void)out_size;

    k_zero_agg1<<<1024, 256>>>();

    // 16 threads per edge
    int sc_blocks = (N_EDGES * 16 + 255) / 256;
    k_scatter1<<<sc_blocks, 256>>>(x, src, dst);

    k_dense1<<<N_NODES / 16, 256>>>(x, W1l, W1r, b1);
    k_dense2<<<N_NODES / 16, 192>>>(W2l, W2r, b2);

    k_scatter2<<<sc_blocks, 256>>>(src, dst);

    k_softmax<<<(N_NODES * 32 + 255) / 256, 256>>>(out);
}

// round 3
// speedup vs baseline: 1.3418x; 1.3418x over previous
#include <cuda_runtime.h>
#include <math.h>

#define N_NODES   100000
#define N_EDGES   1600000
#define IN_F      50
#define AGG_STRIDE 52     // pad 50 -> 52 floats (208B, 16B-aligned rows)
#define HID       64
#define NC        41
#define OSTRIDE   48      // pad 41 -> 48 floats (192B, 16B-aligned rows)

// Scratch (no cudaMalloc allowed)
__device__ __align__(16) float g_agg1[N_NODES * AGG_STRIDE]; // 20.8 MB
__device__ __align__(16) float g_h1[N_NODES * HID];          // 25.6 MB
__device__ __align__(16) float g_z[N_NODES * OSTRIDE];       // 19.2 MB
__device__ __align__(16) float g_o[N_NODES * OSTRIDE];       // 19.2 MB

// ---------------------------------------------------------------------------
__device__ __forceinline__ void red_add_v4(float* p, float4 v) {
    asm volatile("red.global.add.v4.f32 [%0], {%1, %2, %3, %4};"
                 :: "l"(p), "f"(v.x), "f"(v.y), "f"(v.z), "f"(v.w)
                 : "memory");
}

// ---------------------------------------------------------------------------
__global__ void k_zero_agg1() {
    const int total = N_NODES * AGG_STRIDE / 4;
    float4* p = reinterpret_cast<float4*>(g_agg1);
    for (int i = blockIdx.x * blockDim.x + threadIdx.x; i < total;
         i += gridDim.x * blockDim.x)
        p[i] = make_float4(0.f, 0.f, 0.f, 0.f);
}

// ---------------------------------------------------------------------------
// Layer-1 scatter: agg1[dst] += x[src]  (half-warp per edge, float4 atomics)
// ---------------------------------------------------------------------------
__global__ void k_scatter1(const float* __restrict__ x,
                           const int* __restrict__ src,
                           const int* __restrict__ dst) {
    int t = blockIdx.x * blockDim.x + threadIdx.x;
    int e = t >> 4;
    int lane = t & 15;
    if (e >= N_EDGES) return;
    int s = __ldg(&src[e]);
    int d = __ldg(&dst[e]);
    if (lane < 13) {
        const float2* xr = reinterpret_cast<const float2*>(x + (long)s * IN_F);
        float2 a = __ldg(&xr[2 * lane]);
        float2 b = (2 * lane + 1 < 25) ? __ldg(&xr[2 * lane + 1])
                                       : make_float2(0.f, 0.f);
        red_add_v4(g_agg1 + (long)d * AGG_STRIDE + 4 * lane,
                   make_float4(a.x, a.y, b.x, b.y));
    }
}

// ---------------------------------------------------------------------------
// Dense layer 1 (register-blocked): h1 = relu(agg1 @ W1_l + x @ W1_r + b1)
// Tile = 64 nodes, 128 threads = 16 colgroups x 8 node-slots, MB=8 nodes/thread.
// agg and x are transposed into smem so activations load as float4 across nodes.
// ---------------------------------------------------------------------------
#define D1_TILE    64
#define D1_THREADS 128
#define AT_STRIDE  68   // 68*4 = 272B, 16B-aligned; 68 % 32 = 4 (bank spread)
// smem floats: sWl 50*64, sWr 50*64, sB 64, sAT 52*68, sXT 50*68
#define D1_SMEM_FLOATS (50*64*2 + 64 + 52*AT_STRIDE + 50*AT_STRIDE)

__global__ void __launch_bounds__(D1_THREADS)
k_dense1(const float* __restrict__ x,
         const float* __restrict__ W1l,
         const float* __restrict__ W1r,
         const float* __restrict__ b1) {
    extern __shared__ float sm1[];
    float* sWl = sm1;                    // 50*64
    float* sWr = sWl + 50 * HID;         // 50*64
    float* sB  = sWr + 50 * HID;         // 64
    float* sAT = sB + HID;               // 52*68
    float* sXT = sAT + 52 * AT_STRIDE;   // 50*68

    int tid = threadIdx.x;
    int node0 = blockIdx.x * D1_TILE;

    for (int i = tid; i < IN_F * HID; i += D1_THREADS) {
        sWl[i] = W1l[i];
        sWr[i] = W1r[i];
    }
    if (tid < HID) sB[tid] = b1[tid];

    // transpose agg tile: 64 nodes x 13 float4-chunks
    for (int i = tid; i < D1_TILE * 13; i += D1_THREADS) {
        int n  = i / 13;
        int kg = i - n * 13;
        int node = node0 + n;
        float4 v = make_float4(0.f, 0.f, 0.f, 0.f);
        if (node < N_NODES)
            v = *reinterpret_cast<const float4*>(
                &g_agg1[(long)node * AGG_STRIDE + 4 * kg]);
        sAT[(4 * kg + 0) * AT_STRIDE + n] = v.x;
        sAT[(4 * kg + 1) * AT_STRIDE + n] = v.y;
        sAT[(4 * kg + 2) * AT_STRIDE + n] = v.z;
        sAT[(4 * kg + 3) * AT_STRIDE + n] = v.w;
    }
    // transpose x tile: 64 nodes x 25 float2-chunks
    for (int i = tid; i < D1_TILE * 25; i += D1_THREADS) {
        int n  = i / 25;
        int kg = i - n * 25;
        int node = node0 + n;
        float2 v = make_float2(0.f, 0.f);
        if (node < N_NODES)
            v = __ldg(reinterpret_cast<const float2*>(
                x + (long)node * IN_F + 2 * kg));
        sXT[(2 * kg + 0) * AT_STRIDE + n] = v.x;
        sXT[(2 * kg + 1) * AT_STRIDE + n] = v.y;
    }
    __syncthreads();

    int jg = tid & 15;          // cols 4*jg..4*jg+3 (of 64)
    int ms = tid >> 4;          // 0..7
    int nbase = ms * 8;

    float4 acc[8];
#pragma unroll
    for (int i = 0; i < 8; i++) acc[i] = make_float4(0.f, 0.f, 0.f, 0.f);

#pragma unroll 5
    for (int k = 0; k < IN_F; k++) {
        float4 wl = *reinterpret_cast<const float4*>(&sWl[k * HID + 4 * jg]);
        float4 wr = *reinterpret_cast<const float4*>(&sWr[k * HID + 4 * jg]);
        float4 a0 = *reinterpret_cast<const float4*>(&sAT[k * AT_STRIDE + nbase]);
        float4 a1 = *reinterpret_cast<const float4*>(&sAT[k * AT_STRIDE + nbase + 4]);
        float4 x0 = *reinterpret_cast<const float4*>(&sXT[k * AT_STRIDE + nbase]);
        float4 x1 = *reinterpret_cast<const float4*>(&sXT[k * AT_STRIDE + nbase + 4]);
        float av[8] = {a0.x, a0.y, a0.z, a0.w, a1.x, a1.y, a1.z, a1.w};
        float xv[8] = {x0.x, x0.y, x0.z, x0.w, x1.x, x1.y, x1.z, x1.w};
#pragma unroll
        for (int i = 0; i < 8; i++) {
            acc[i].x += av[i] * wl.x + xv[i] * wr.x;
            acc[i].y += av[i] * wl.y + xv[i] * wr.y;
            acc[i].z += av[i] * wl.z + xv[i] * wr.z;
            acc[i].w += av[i] * wl.w + xv[i] * wr.w;
        }
    }

    float4 bb = *reinterpret_cast<const float4*>(&sB[4 * jg]);
#pragma unroll
    for (int i = 0; i < 8; i++) {
        int node = node0 + nbase + i;
        if (node < N_NODES) {
            float4 r;
            r.x = fmaxf(acc[i].x + bb.x, 0.f);
            r.y = fmaxf(acc[i].y + bb.y, 0.f);
            r.z = fmaxf(acc[i].z + bb.z, 0.f);
            r.w = fmaxf(acc[i].w + bb.w, 0.f);
            *reinterpret_cast<float4*>(&g_h1[(long)node * HID + 4 * jg]) = r;
        }
    }
}

// ---------------------------------------------------------------------------
// Dense layer 2 (register-blocked):
//   z = h1 @ W2_l   ;   o = h1 @ W2_r + b2
// Tile = 128 nodes, 192 threads = 4 subtiles x (12 colgroups x 4 node-slots),
// MB=8 nodes/thread.
// ---------------------------------------------------------------------------
#define D2_TILE    128
#define D2_THREADS 192
#define HT_STRIDE  132  // 132*4 = 528B, 16B-aligned; 132 % 32 = 4
// smem floats: sWl 64*48, sWr 64*48, sB 48, sHT 64*132
#define D2_SMEM_FLOATS (HID*OSTRIDE*2 + OSTRIDE + HID*HT_STRIDE)

__global__ void __launch_bounds__(D2_THREADS)
k_dense2(const float* __restrict__ W2l,
         const float* __restrict__ W2r,
         const float* __restrict__ b2) {
    extern __shared__ float sm2[];
    float* sWl = sm2;                    // 64*48
    float* sWr = sWl + HID * OSTRIDE;    // 64*48
    float* sB  = sWr + HID * OSTRIDE;    // 48
    float* sHT = sB + OSTRIDE;           // 64*132

    int tid = threadIdx.x;
    int node0 = blockIdx.x * D2_TILE;

    for (int i = tid; i < HID * OSTRIDE; i += D2_THREADS) {
        int k = i / OSTRIDE;
        int c = i - k * OSTRIDE;
        sWl[i] = (c < NC) ? W2l[k * NC + c] : 0.f;
        sWr[i] = (c < NC) ? W2r[k * NC + c] : 0.f;
    }
    if (tid < OSTRIDE) sB[tid] = (tid < NC) ? b2[tid] : 0.f;

    // transpose h1 tile: 128 nodes x 16 float4-chunks
    for (int i = tid; i < D2_TILE * 16; i += D2_THREADS) {
        int n  = i >> 4;
        int kg = i & 15;
        int node = node0 + n;
        float4 v = make_float4(0.f, 0.f, 0.f, 0.f);
        if (node < N_NODES)
            v = *reinterpret_cast<const float4*>(
                &g_h1[(long)node * HID + 4 * kg]);
        sHT[(4 * kg + 0) * HT_STRIDE + n] = v.x;
        sHT[(4 * kg + 1) * HT_STRIDE + n] = v.y;
        sHT[(4 * kg + 2) * HT_STRIDE + n] = v.z;
        sHT[(4 * kg + 3) * HT_STRIDE + n] = v.w;
    }
    __syncthreads();

    int st = tid / 48;          // subtile 0..3 (32 nodes each)
    int r  = tid - st * 48;
    int ms = r / 12;            // 0..3
    int jg = r - ms * 12;       // cols 4*jg..4*jg+3 (of 48)
    int nbase = st * 32 + ms * 8;

    float4 az[8], ao[8];
#pragma unroll
    for (int i = 0; i < 8; i++) {
        az[i] = make_float4(0.f, 0.f, 0.f, 0.f);
        ao[i] = make_float4(0.f, 0.f, 0.f, 0.f);
    }

#pragma unroll 4
    for (int k = 0; k < HID; k++) {
        float4 wl = *reinterpret_cast<const float4*>(&sWl[k * OSTRIDE + 4 * jg]);
        float4 wr = *reinterpret_cast<const float4*>(&sWr[k * OSTRIDE + 4 * jg]);
        float4 h0 = *reinterpret_cast<const float4*>(&sHT[k * HT_STRIDE + nbase]);
        float4 h1v = *reinterpret_cast<const float4*>(&sHT[k * HT_STRIDE + nbase + 4]);
        float hv[8] = {h0.x, h0.y, h0.z, h0.w, h1v.x, h1v.y, h1v.z, h1v.w};
#pragma unroll
        for (int i = 0; i < 8; i++) {
            az[i].x += hv[i] * wl.x; az[i].y += hv[i] * wl.y;
            az[i].z += hv[i] * wl.z; az[i].w += hv[i] * wl.w;
            ao[i].x += hv[i] * wr.x; ao[i].y += hv[i] * wr.y;
            ao[i].z += hv[i] * wr.z; ao[i].w += hv[i] * wr.w;
        }
    }

    float4 bb = *reinterpret_cast<const float4*>(&sB[4 * jg]);
#pragma unroll
    for (int i = 0; i < 8; i++) {
        int node = node0 + nbase + i;
        if (node < N_NODES) {
            long off = (long)node * OSTRIDE + 4 * jg;
            *reinterpret_cast<float4*>(&g_z[off]) = az[i];
            float4 o;
            o.x = ao[i].x + bb.x; o.y = ao[i].y + bb.y;
            o.z = ao[i].z + bb.z; o.w = ao[i].w + bb.w;
            *reinterpret_cast<float4*>(&g_o[off]) = o;
        }
    }
}

// ---------------------------------------------------------------------------
// Layer-2 scatter: o[dst] += z[src]
// ---------------------------------------------------------------------------
__global__ void k_scatter2(const int* __restrict__ src,
                           const int* __restrict__ dst) {
    int t = blockIdx.x * blockDim.x + threadIdx.x;
    int e = t >> 4;
    int lane = t & 15;
    if (e >= N_EDGES) return;
    int s = __ldg(&src[e]);
    int d = __ldg(&dst[e]);
    if (lane < 12) {
        float4 v = *reinterpret_cast<const float4*>(
            &g_z[(long)s * OSTRIDE + 4 * lane]);
        red_add_v4(&g_o[(long)d * OSTRIDE + 4 * lane], v);
    }
}

// ---------------------------------------------------------------------------
// log_softmax over 41 classes, warp per node
// ---------------------------------------------------------------------------
__global__ void k_softmax(float* __restrict__ out) {
    int t = blockIdx.x * blockDim.x + threadIdx.x;
    int n = t >> 5;
    int lane = t & 31;
    if (n >= N_NODES) return;

    const float* row = &g_o[(long)n * OSTRIDE];
    float v0 = row[lane];
    float v1 = (lane < NC - 32) ? row[32 + lane] : -INFINITY;

    float mx = fmaxf(v0, v1);
#pragma unroll
    for (int off = 16; off > 0; off >>= 1)
        mx = fmaxf(mx, __shfl_xor_sync(0xFFFFFFFFu, mx, off));

    float sum = expf(v0 - mx) + ((lane < NC - 32) ? expf(v1 - mx) : 0.f);
#pragma unroll
    for (int off = 16; off > 0; off >>= 1)
        sum += __shfl_xor_sync(0xFFFFFFFFu, sum, off);

    float lse = mx + logf(sum);
    out[(long)n * NC + lane] = v0 - lse;
    if (lane < NC - 32)
        out[(long)n * NC + 32 + lane] = v1 - lse;
}

// ---------------------------------------------------------------------------
extern "C" void kernel_launch(void* const* d_in, const int* in_sizes, int n_in,
                              void* d_out, int out_size) {
    const float* x   = (const float*)d_in[0];
    const float* W1l = (const float*)d_in[1];
    const float* W1r = (const float*)d_in[2];
    const float* b1  = (const float*)d_in[3];
    const float* W2l = (const float*)d_in[4];
    const float* W2r = (const float*)d_in[5];
    const float* b2  = (const float*)d_in[6];
    const int*   src = (const int*)d_in[7];
    const int*   dst = (const int*)d_in[8];
    float* out = (float*)d_out;

    (void)in_sizes; (void)n_in; (void)out_size;

    const int d1_smem = D1_SMEM_FLOATS * 4;
    const int d2_smem = D2_SMEM_FLOATS * 4;
    cudaFuncSetAttribute(k_dense1, cudaFuncAttributeMaxDynamicSharedMemorySize,
                         d1_smem);
    cudaFuncSetAttribute(k_dense2, cudaFuncAttributeMaxDynamicSharedMemorySize,
                         d2_smem);

    k_zero_agg1<<<1024, 256>>>();

    int sc_blocks = (N_EDGES * 16 + 255) / 256;
    k_scatter1<<<sc_blocks, 256>>>(x, src, dst);

    k_dense1<<<(N_NODES + D1_TILE - 1) / D1_TILE, D1_THREADS, d1_smem>>>(
        x, W1l, W1r, b1);
    k_dense2<<<(N_NODES + D2_TILE - 1) / D2_TILE, D2_THREADS, d2_smem>>>(
        W2l, W2r, b2);

    k_scatter2<<<sc_blocks, 256>>>(src, dst);

    k_softmax<<<(N_NODES * 32 + 255) / 256, 256>>>(out);
}

// round 4
// speedup vs baseline: 1.7506x; 1.3047x over previous
#include <cuda_runtime.h>
#include <math.h>

#define N_NODES   100000
#define N_EDGES   1600000
#define IN_F      50
#define AGG_STRIDE 52     // pad 50 -> 52 floats (208B, 16B-aligned rows)
#define HID       64
#define NC        41
#define OSTRIDE   48      // pad 41 -> 48 floats (192B, 16B-aligned rows)

// Scratch (no cudaMalloc allowed)
__device__ __align__(16) float g_agg1[N_NODES * AGG_STRIDE]; // 20.8 MB
__device__ __align__(16) float g_h1[N_NODES * HID];          // 25.6 MB
__device__ __align__(16) float g_z[N_NODES * OSTRIDE];       // 19.2 MB
__device__ __align__(16) float g_o[N_NODES * OSTRIDE];       // 19.2 MB

// CSR scratch
#define SCAN_B   1024
#define SCAN_NB  98            // 98*1024 = 100352 >= N_NODES
__device__ int g_cnt[SCAN_NB * SCAN_B];
__device__ int g_off[N_NODES + 1];
__device__ int g_cur[N_NODES];
__device__ int g_bsum[SCAN_NB];
__device__ int g_ssrc[N_EDGES];

// ---------------------------------------------------------------------------
// CSR construction
// ---------------------------------------------------------------------------
__global__ void k_zero_cnt() {
    int i = blockIdx.x * blockDim.x + threadIdx.x;
    if (i < SCAN_NB * SCAN_B) g_cnt[i] = 0;
}

__global__ void k_hist(const int* __restrict__ dst) {
    for (int e = blockIdx.x * blockDim.x + threadIdx.x; e < N_EDGES;
         e += gridDim.x * blockDim.x)
        atomicAdd(&g_cnt[__ldg(&dst[e])], 1);
}

// per-block exclusive scan of g_cnt; block total -> g_bsum
__global__ void __launch_bounds__(SCAN_B) k_scan_block() {
    __shared__ int s[SCAN_B];
    int tid = threadIdx.x;
    int i = blockIdx.x * SCAN_B + tid;
    int v = g_cnt[i];
    s[tid] = v;
    __syncthreads();
#pragma unroll
    for (int off = 1; off < SCAN_B; off <<= 1) {
        int t = 0;
        if (tid >= off) t = s[tid - off];
        __syncthreads();
        if (tid >= off) s[tid] += t;
        __syncthreads();
    }
    if (i <= N_NODES) {
        // exclusive value (pre block-offset); store in g_off
        if (i < N_NODES) g_off[i] = s[tid] - v;
    }
    if (tid == SCAN_B - 1) g_bsum[blockIdx.x] = s[tid];
}

__global__ void k_scan_top() {
    if (threadIdx.x == 0 && blockIdx.x == 0) {
        int run = 0;
        for (int b = 0; b < SCAN_NB; b++) {
            int t = g_bsum[b];
            g_bsum[b] = run;
            run += t;
        }
    }
}

__global__ void __launch_bounds__(SCAN_B) k_scan_add() {
    int tid = threadIdx.x;
    int i = blockIdx.x * SCAN_B + tid;
    if (i < N_NODES) {
        int v = g_off[i] + g_bsum[blockIdx.x];
        g_off[i] = v;
        g_cur[i] = v;
    }
    if (i == 0) g_off[N_NODES] = N_EDGES;
}

__global__ void k_bucket(const int* __restrict__ src,
                         const int* __restrict__ dst) {
    for (int e = blockIdx.x * blockDim.x + threadIdx.x; e < N_EDGES;
         e += gridDim.x * blockDim.x) {
        int d = __ldg(&dst[e]);
        int pos = atomicAdd(&g_cur[d], 1);
        g_ssrc[pos] = __ldg(&src[e]);
    }
}

// ---------------------------------------------------------------------------
// Layer-1 aggregation (gather, warp per node, register accumulation)
//   g_agg1[n] = sum_{e: dst=n} x[src[e]]
// ---------------------------------------------------------------------------
__global__ void __launch_bounds__(256) k_agg1(const float* __restrict__ x) {
    int warp = (blockIdx.x * blockDim.x + threadIdx.x) >> 5;
    int lane = threadIdx.x & 31;
    if (warp >= N_NODES) return;
    int n = warp;

    int beg = g_off[n];
    int end = g_off[n + 1];

    float a0 = 0.f, a1 = 0.f;
    int e = beg;
    int s_next = (e < end) ? __ldg(&g_ssrc[e]) : 0;
    while (e < end) {
        int s = s_next;
        e++;
        if (e < end) s_next = __ldg(&g_ssrc[e]);
        const float* xr = x + (long)s * IN_F;
        a0 += __ldg(&xr[lane]);
        if (lane < IN_F - 32) a1 += __ldg(&xr[32 + lane]);
    }

    float* ar = &g_agg1[(long)n * AGG_STRIDE];
    ar[lane] = a0;
    if (lane < IN_F - 32) ar[32 + lane] = a1;
}

// ---------------------------------------------------------------------------
// Dense layer 1 (register-blocked): h1 = relu(agg1 @ W1_l + x @ W1_r + b1)
// ---------------------------------------------------------------------------
#define D1_TILE    64
#define D1_THREADS 128
#define AT_STRIDE  68
#define D1_SMEM_FLOATS (50*64*2 + 64 + 52*AT_STRIDE + 50*AT_STRIDE)

__global__ void __launch_bounds__(D1_THREADS)
k_dense1(const float* __restrict__ x,
         const float* __restrict__ W1l,
         const float* __restrict__ W1r,
         const float* __restrict__ b1) {
    extern __shared__ float sm1[];
    float* sWl = sm1;
    float* sWr = sWl + 50 * HID;
    float* sB  = sWr + 50 * HID;
    float* sAT = sB + HID;
    float* sXT = sAT + 52 * AT_STRIDE;

    int tid = threadIdx.x;
    int node0 = blockIdx.x * D1_TILE;

    for (int i = tid; i < IN_F * HID; i += D1_THREADS) {
        sWl[i] = W1l[i];
        sWr[i] = W1r[i];
    }
    if (tid < HID) sB[tid] = b1[tid];

    for (int i = tid; i < D1_TILE * 13; i += D1_THREADS) {
        int n  = i / 13;
        int kg = i - n * 13;
        int node = node0 + n;
        float4 v = make_float4(0.f, 0.f, 0.f, 0.f);
        if (node < N_NODES)
            v = *reinterpret_cast<const float4*>(
                &g_agg1[(long)node * AGG_STRIDE + 4 * kg]);
        sAT[(4 * kg + 0) * AT_STRIDE + n] = v.x;
        sAT[(4 * kg + 1) * AT_STRIDE + n] = v.y;
        sAT[(4 * kg + 2) * AT_STRIDE + n] = v.z;
        sAT[(4 * kg + 3) * AT_STRIDE + n] = v.w;
    }
    for (int i = tid; i < D1_TILE * 25; i += D1_THREADS) {
        int n  = i / 25;
        int kg = i - n * 25;
        int node = node0 + n;
        float2 v = make_float2(0.f, 0.f);
        if (node < N_NODES)
            v = __ldg(reinterpret_cast<const float2*>(
                x + (long)node * IN_F + 2 * kg));
        sXT[(2 * kg + 0) * AT_STRIDE + n] = v.x;
        sXT[(2 * kg + 1) * AT_STRIDE + n] = v.y;
    }
    __syncthreads();

    int jg = tid & 15;
    int ms = tid >> 4;
    int nbase = ms * 8;

    float4 acc[8];
#pragma unroll
    for (int i = 0; i < 8; i++) acc[i] = make_float4(0.f, 0.f, 0.f, 0.f);

#pragma unroll 5
    for (int k = 0; k < IN_F; k++) {
        float4 wl = *reinterpret_cast<const float4*>(&sWl[k * HID + 4 * jg]);
        float4 wr = *reinterpret_cast<const float4*>(&sWr[k * HID + 4 * jg]);
        float4 a0 = *reinterpret_cast<const float4*>(&sAT[k * AT_STRIDE + nbase]);
        float4 a1 = *reinterpret_cast<const float4*>(&sAT[k * AT_STRIDE + nbase + 4]);
        float4 x0 = *reinterpret_cast<const float4*>(&sXT[k * AT_STRIDE + nbase]);
        float4 x1 = *reinterpret_cast<const float4*>(&sXT[k * AT_STRIDE + nbase + 4]);
        float av[8] = {a0.x, a0.y, a0.z, a0.w, a1.x, a1.y, a1.z, a1.w};
        float xv[8] = {x0.x, x0.y, x0.z, x0.w, x1.x, x1.y, x1.z, x1.w};
#pragma unroll
        for (int i = 0; i < 8; i++) {
            acc[i].x += av[i] * wl.x + xv[i] * wr.x;
            acc[i].y += av[i] * wl.y + xv[i] * wr.y;
            acc[i].z += av[i] * wl.z + xv[i] * wr.z;
            acc[i].w += av[i] * wl.w + xv[i] * wr.w;
        }
    }

    float4 bb = *reinterpret_cast<const float4*>(&sB[4 * jg]);
#pragma unroll
    for (int i = 0; i < 8; i++) {
        int node = node0 + nbase + i;
        if (node < N_NODES) {
            float4 r;
            r.x = fmaxf(acc[i].x + bb.x, 0.f);
            r.y = fmaxf(acc[i].y + bb.y, 0.f);
            r.z = fmaxf(acc[i].z + bb.z, 0.f);
            r.w = fmaxf(acc[i].w + bb.w, 0.f);
            *reinterpret_cast<float4*>(&g_h1[(long)node * HID + 4 * jg]) = r;
        }
    }
}

// ---------------------------------------------------------------------------
// Dense layer 2 (register-blocked): z = h1 @ W2_l ; o = h1 @ W2_r + b2
// ---------------------------------------------------------------------------
#define D2_TILE    128
#define D2_THREADS 192
#define HT_STRIDE  132
#define D2_SMEM_FLOATS (HID*OSTRIDE*2 + OSTRIDE + HID*HT_STRIDE)

__global__ void __launch_bounds__(D2_THREADS)
k_dense2(const float* __restrict__ W2l,
         const float* __restrict__ W2r,
         const float* __restrict__ b2) {
    extern __shared__ float sm2[];
    float* sWl = sm2;
    float* sWr = sWl + HID * OSTRIDE;
    float* sB  = sWr + HID * OSTRIDE;
    float* sHT = sB + OSTRIDE;

    int tid = threadIdx.x;
    int node0 = blockIdx.x * D2_TILE;

    for (int i = tid; i < HID * OSTRIDE; i += D2_THREADS) {
        int k = i / OSTRIDE;
        int c = i - k * OSTRIDE;
        sWl[i] = (c < NC) ? W2l[k * NC + c] : 0.f;
        sWr[i] = (c < NC) ? W2r[k * NC + c] : 0.f;
    }
    if (tid < OSTRIDE) sB[tid] = (tid < NC) ? b2[tid] : 0.f;

    for (int i = tid; i < D2_TILE * 16; i += D2_THREADS) {
        int n  = i >> 4;
        int kg = i & 15;
        int node = node0 + n;
        float4 v = make_float4(0.f, 0.f, 0.f, 0.f);
        if (node < N_NODES)
            v = *reinterpret_cast<const float4*>(
                &g_h1[(long)node * HID + 4 * kg]);
        sHT[(4 * kg + 0) * HT_STRIDE + n] = v.x;
        sHT[(4 * kg + 1) * HT_STRIDE + n] = v.y;
        sHT[(4 * kg + 2) * HT_STRIDE + n] = v.z;
        sHT[(4 * kg + 3) * HT_STRIDE + n] = v.w;
    }
    __syncthreads();

    int st = tid / 48;
    int r  = tid - st * 48;
    int ms = r / 12;
    int jg = r - ms * 12;
    int nbase = st * 32 + ms * 8;

    float4 az[8], ao[8];
#pragma unroll
    for (int i = 0; i < 8; i++) {
        az[i] = make_float4(0.f, 0.f, 0.f, 0.f);
        ao[i] = make_float4(0.f, 0.f, 0.f, 0.f);
    }

#pragma unroll 4
    for (int k = 0; k < HID; k++) {
        float4 wl = *reinterpret_cast<const float4*>(&sWl[k * OSTRIDE + 4 * jg]);
        float4 wr = *reinterpret_cast<const float4*>(&sWr[k * OSTRIDE + 4 * jg]);
        float4 h0 = *reinterpret_cast<const float4*>(&sHT[k * HT_STRIDE + nbase]);
        float4 h1v = *reinterpret_cast<const float4*>(&sHT[k * HT_STRIDE + nbase + 4]);
        float hv[8] = {h0.x, h0.y, h0.z, h0.w, h1v.x, h1v.y, h1v.z, h1v.w};
#pragma unroll
        for (int i = 0; i < 8; i++) {
            az[i].x += hv[i] * wl.x; az[i].y += hv[i] * wl.y;
            az[i].z += hv[i] * wl.z; az[i].w += hv[i] * wl.w;
            ao[i].x += hv[i] * wr.x; ao[i].y += hv[i] * wr.y;
            ao[i].z += hv[i] * wr.z; ao[i].w += hv[i] * wr.w;
        }
    }

    float4 bb = *reinterpret_cast<const float4*>(&sB[4 * jg]);
#pragma unroll
    for (int i = 0; i < 8; i++) {
        int node = node0 + nbase + i;
        if (node < N_NODES) {
            long off = (long)node * OSTRIDE + 4 * jg;
            *reinterpret_cast<float4*>(&g_z[off]) = az[i];
            float4 o;
            o.x = ao[i].x + bb.x; o.y = ao[i].y + bb.y;
            o.z = ao[i].z + bb.z; o.w = ao[i].w + bb.w;
            *reinterpret_cast<float4*>(&g_o[off]) = o;
        }
    }
}

// ---------------------------------------------------------------------------
// Layer-2 aggregation + log_softmax fused (gather, warp per node)
//   o[n] = g_o[n] + sum_{e: dst=n} g_z[src[e]];  out[n] = log_softmax(o[n])
// ---------------------------------------------------------------------------
__global__ void __launch_bounds__(256) k_agg2_softmax(float* __restrict__ out) {
    int warp = (blockIdx.x * blockDim.x + threadIdx.x) >> 5;
    int lane = threadIdx.x & 31;
    if (warp >= N_NODES) return;
    int n = warp;

    const float* orow = &g_o[(long)n * OSTRIDE];
    float o0 = orow[lane];                          // classes 0..31
    float o1 = (lane < NC - 32) ? orow[32 + lane] : 0.f; // classes 32..40

    int beg = g_off[n];
    int end = g_off[n + 1];
    int e = beg;
    int s_next = (e < end) ? __ldg(&g_ssrc[e]) : 0;
    while (e < end) {
        int s = s_next;
        e++;
        if (e < end) s_next = __ldg(&g_ssrc[e]);
        const float* zr = &g_z[(long)s * OSTRIDE];
        o0 += __ldg(&zr[lane]);
        if (lane < NC - 32) o1 += __ldg(&zr[32 + lane]);
    }

    float mx = fmaxf(o0, (lane < NC - 32) ? o1 : -INFINITY);
#pragma unroll
    for (int off = 16; off > 0; off >>= 1)
        mx = fmaxf(mx, __shfl_xor_sync(0xFFFFFFFFu, mx, off));

    float sum = expf(o0 - mx) + ((lane < NC - 32) ? expf(o1 - mx) : 0.f);
#pragma unroll
    for (int off = 16; off > 0; off >>= 1)
        sum += __shfl_xor_sync(0xFFFFFFFFu, sum, off);

    float lse = mx + logf(sum);
    out[(long)n * NC + lane] = o0 - lse;
    if (lane < NC - 32)
        out[(long)n * NC + 32 + lane] = o1 - lse;
}

// ---------------------------------------------------------------------------
extern "C" void kernel_launch(void* const* d_in, const int* in_sizes, int n_in,
                              void* d_out, int out_size) {
    const float* x   = (const float*)d_in[0];
    const float* W1l = (const float*)d_in[1];
    const float* W1r = (const float*)d_in[2];
    const float* b1  = (const float*)d_in[3];
    const float* W2l = (const float*)d_in[4];
    const float* W2r = (const float*)d_in[5];
    const float* b2  = (const float*)d_in[6];
    const int*   src = (const int*)d_in[7];
    const int*   dst = (const int*)d_in[8];
    float* out = (float*)d_out;

    (void)in_sizes; (void)n_in; (void)out_size;

    const int d1_smem = D1_SMEM_FLOATS * 4;
    const int d2_smem = D2_SMEM_FLOATS * 4;
    cudaFuncSetAttribute(k_dense1, cudaFuncAttributeMaxDynamicSharedMemorySize,
                         d1_smem);
    cudaFuncSetAttribute(k_dense2, cudaFuncAttributeMaxDynamicSharedMemorySize,
                         d2_smem);

    // --- CSR build ---
    k_zero_cnt<<<(SCAN_NB * SCAN_B + 255) / 256, 256>>>();
    k_hist<<<1480, 256>>>(dst);
    k_scan_block<<<SCAN_NB, SCAN_B>>>();
    k_scan_top<<<1, 32>>>();
    k_scan_add<<<SCAN_NB, SCAN_B>>>();
    k_bucket<<<1480, 256>>>(src, dst);

    // --- Layer 1 ---
    k_agg1<<<(N_NODES + 7) / 8, 256>>>(x);
    k_dense1<<<(N_NODES + D1_TILE - 1) / D1_TILE, D1_THREADS, d1_smem>>>(
        x, W1l, W1r, b1);

    // --- Layer 2 ---
    k_dense2<<<(N_NODES + D2_TILE - 1) / D2_TILE, D2_THREADS, d2_smem>>>(
        W2l, W2r, b2);
    k_agg2_softmax<<<(N_NODES + 7) / 8, 256>>>(out);
}

// round 5
// speedup vs baseline: 1.8502x; 1.0569x over previous
#include <cuda_runtime.h>
#include <math.h>

#define N_NODES   100000
#define N_EDGES   1600000
#define IN_F      50
#define AGG_STRIDE 52     // pad 50 -> 52 floats (208B, 16B-aligned rows)
#define HID       64
#define NC        41
#define OSTRIDE   48      // pad 41 -> 48 floats (192B, 16B-aligned rows)

// Scratch (no cudaMalloc allowed)
__device__ __align__(16) float g_agg1[N_NODES * AGG_STRIDE]; // 20.8 MB
__device__ __align__(16) float g_h1[N_NODES * HID];          // 25.6 MB
__device__ __align__(16) float g_z[N_NODES * OSTRIDE];       // 19.2 MB
__device__ __align__(16) float g_o[N_NODES * OSTRIDE];       // 19.2 MB

// CSR scratch
#define SCAN_B   1024
#define SCAN_NB  98            // 98*1024 = 100352 >= N_NODES
__device__ int g_cnt[SCAN_NB * SCAN_B];
__device__ int g_off[N_NODES + 1];
__device__ int g_cur[N_NODES];
__device__ int g_bsum[SCAN_NB];
__device__ int g_ssrc[N_EDGES];

// ---------------------------------------------------------------------------
// f32x2 packed-math helpers (sm_103a; ptxas never auto-fuses these)
// ---------------------------------------------------------------------------
__device__ __forceinline__ unsigned long long pk2(float a, float b) {
    unsigned long long r;
    asm("mov.b64 %0, {%1, %2};" : "=l"(r) : "f"(a), "f"(b));
    return r;
}
__device__ __forceinline__ void fma2(unsigned long long& d,
                                     unsigned long long a,
                                     unsigned long long b) {
    asm("fma.rn.f32x2 %0, %1, %2, %0;" : "+l"(d) : "l"(a), "l"(b));
}
__device__ __forceinline__ float2 up2(unsigned long long v) {
    float2 r;
    asm("mov.b64 {%0, %1}, %2;" : "=f"(r.x), "=f"(r.y) : "l"(v));
    return r;
}

// ---------------------------------------------------------------------------
// CSR construction
// ---------------------------------------------------------------------------
__global__ void k_zero_cnt() {
    int i = blockIdx.x * blockDim.x + threadIdx.x;
    if (i < SCAN_NB * SCAN_B) g_cnt[i] = 0;
}

__global__ void k_hist(const int* __restrict__ dst) {
    for (int e = blockIdx.x * blockDim.x + threadIdx.x; e < N_EDGES;
         e += gridDim.x * blockDim.x)
        atomicAdd(&g_cnt[__ldg(&dst[e])], 1);
}

// per-block exclusive scan of g_cnt via shfl; block total -> g_bsum
__global__ void __launch_bounds__(SCAN_B) k_scan_block() {
    __shared__ int wsum[32];
    int tid  = threadIdx.x;
    int lane = tid & 31;
    int wid  = tid >> 5;
    int i = blockIdx.x * SCAN_B + tid;
    int v = g_cnt[i];

    int inc = v;
#pragma unroll
    for (int off = 1; off < 32; off <<= 1) {
        int t = __shfl_up_sync(0xFFFFFFFFu, inc, off);
        if (lane >= off) inc += t;
    }
    if (lane == 31) wsum[wid] = inc;
    __syncthreads();
    if (wid == 0) {
        int w = wsum[lane];
        int winc = w;
#pragma unroll
        for (int off = 1; off < 32; off <<= 1) {
            int t = __shfl_up_sync(0xFFFFFFFFu, winc, off);
            if (lane >= off) winc += t;
        }
        wsum[lane] = winc - w;   // exclusive warp prefix
    }
    __syncthreads();

    int excl = inc - v + wsum[wid];
    if (i < N_NODES) g_off[i] = excl;
    if (tid == SCAN_B - 1) g_bsum[blockIdx.x] = excl + v;  // block total
}

// parallel scan over the 98 block sums
__global__ void __launch_bounds__(128) k_scan_top() {
    __shared__ int s[128];
    int tid = threadIdx.x;
    int v = (tid < SCAN_NB) ? g_bsum[tid] : 0;
    s[tid] = v;
    __syncthreads();
#pragma unroll
    for (int off = 1; off < 128; off <<= 1) {
        int t = (tid >= off) ? s[tid - off] : 0;
        __syncthreads();
        s[tid] += t;
        __syncthreads();
    }
    if (tid < SCAN_NB) g_bsum[tid] = s[tid] - v;  // exclusive
}

__global__ void __launch_bounds__(SCAN_B) k_scan_add() {
    int tid = threadIdx.x;
    int i = blockIdx.x * SCAN_B + tid;
    if (i < N_NODES) {
        int v = g_off[i] + g_bsum[blockIdx.x];
        g_off[i] = v;
        g_cur[i] = v;
    }
    if (i == 0) g_off[N_NODES] = N_EDGES;
}

__global__ void k_bucket(const int* __restrict__ src,
                         const int* __restrict__ dst) {
    for (int e = blockIdx.x * blockDim.x + threadIdx.x; e < N_EDGES;
         e += gridDim.x * blockDim.x) {
        int d = __ldg(&dst[e]);
        int pos = atomicAdd(&g_cur[d], 1);
        g_ssrc[pos] = __ldg(&src[e]);
    }
}

// ---------------------------------------------------------------------------
// Layer-1 aggregation (gather, warp per node, 2-edge pipelined)
// ---------------------------------------------------------------------------
__global__ void __launch_bounds__(256) k_agg1(const float* __restrict__ x) {
    int warp = (blockIdx.x * blockDim.x + threadIdx.x) >> 5;
    int lane = threadIdx.x & 31;
    if (warp >= N_NODES) return;
    int n = warp;

    int beg = g_off[n];
    int end = g_off[n + 1];

    float a0 = 0.f, a1 = 0.f;
    int e = beg;
    int sA = (e     < end) ? __ldg(&g_ssrc[e])     : 0;
    int sB = (e + 1 < end) ? __ldg(&g_ssrc[e + 1]) : 0;
    while (e < end) {
        int s0 = sA, s1 = sB;
        float m1 = (e + 1 < end) ? 1.f : 0.f;
        sA = (e + 2 < end) ? __ldg(&g_ssrc[e + 2]) : 0;
        sB = (e + 3 < end) ? __ldg(&g_ssrc[e + 3]) : 0;
        const float* x0 = x + (long)s0 * IN_F;
        const float* x1 = x + (long)s1 * IN_F;
        float v00 = __ldg(&x0[lane]);
        float v10 = __ldg(&x1[lane]);
        a0 += v00 + m1 * v10;
        if (lane < IN_F - 32) {
            float v01 = __ldg(&x0[32 + lane]);
            float v11 = __ldg(&x1[32 + lane]);
            a1 += v01 + m1 * v11;
        }
        e += 2;
    }

    float* ar = &g_agg1[(long)n * AGG_STRIDE];
    ar[lane] = a0;
    if (lane < IN_F - 32) ar[32 + lane] = a1;
}

// ---------------------------------------------------------------------------
// Dense layer 1 (register-blocked, f32x2): h1 = relu(agg1@W1_l + x@W1_r + b1)
// ---------------------------------------------------------------------------
#define D1_TILE    64
#define D1_THREADS 128
#define AT_STRIDE  68
#define D1_SMEM_FLOATS (50*64*2 + 64 + 52*AT_STRIDE + 50*AT_STRIDE)

__global__ void __launch_bounds__(D1_THREADS)
k_dense1(const float* __restrict__ x,
         const float* __restrict__ W1l,
         const float* __restrict__ W1r,
         const float* __restrict__ b1) {
    extern __shared__ float sm1[];
    float* sWl = sm1;
    float* sWr = sWl + 50 * HID;
    float* sB  = sWr + 50 * HID;
    float* sAT = sB + HID;
    float* sXT = sAT + 52 * AT_STRIDE;

    int tid = threadIdx.x;
    int node0 = blockIdx.x * D1_TILE;

    for (int i = tid; i < IN_F * HID; i += D1_THREADS) {
        sWl[i] = W1l[i];
        sWr[i] = W1r[i];
    }
    if (tid < HID) sB[tid] = b1[tid];

    for (int i = tid; i < D1_TILE * 13; i += D1_THREADS) {
        int n  = i / 13;
        int kg = i - n * 13;
        int node = node0 + n;
        float4 v = make_float4(0.f, 0.f, 0.f, 0.f);
        if (node < N_NODES)
            v = *reinterpret_cast<const float4*>(
                &g_agg1[(long)node * AGG_STRIDE + 4 * kg]);
        sAT[(4 * kg + 0) * AT_STRIDE + n] = v.x;
        sAT[(4 * kg + 1) * AT_STRIDE + n] = v.y;
        sAT[(4 * kg + 2) * AT_STRIDE + n] = v.z;
        sAT[(4 * kg + 3) * AT_STRIDE + n] = v.w;
    }
    for (int i = tid; i < D1_TILE * 25; i += D1_THREADS) {
        int n  = i / 25;
        int kg = i - n * 25;
        int node = node0 + n;
        float2 v = make_float2(0.f, 0.f);
        if (node < N_NODES)
            v = __ldg(reinterpret_cast<const float2*>(
                x + (long)node * IN_F + 2 * kg));
        sXT[(2 * kg + 0) * AT_STRIDE + n] = v.x;
        sXT[(2 * kg + 1) * AT_STRIDE + n] = v.y;
    }
    __syncthreads();

    int jg = tid & 15;
    int ms = tid >> 4;
    int nbase = ms * 8;

    unsigned long long acc01[8], acc23[8];
#pragma unroll
    for (int i = 0; i < 8; i++) { acc01[i] = 0ULL; acc23[i] = 0ULL; }

#pragma unroll 5
    for (int k = 0; k < IN_F; k++) {
        ulonglong2 wl = *reinterpret_cast<const ulonglong2*>(&sWl[k * HID + 4 * jg]);
        ulonglong2 wr = *reinterpret_cast<const ulonglong2*>(&sWr[k * HID + 4 * jg]);
        float4 a0 = *reinterpret_cast<const float4*>(&sAT[k * AT_STRIDE + nbase]);
        float4 a1 = *reinterpret_cast<const float4*>(&sAT[k * AT_STRIDE + nbase + 4]);
        float4 x0 = *reinterpret_cast<const float4*>(&sXT[k * AT_STRIDE + nbase]);
        float4 x1 = *reinterpret_cast<const float4*>(&sXT[k * AT_STRIDE + nbase + 4]);
        float av[8] = {a0.x, a0.y, a0.z, a0.w, a1.x, a1.y, a1.z, a1.w};
        float xv[8] = {x0.x, x0.y, x0.z, x0.w, x1.x, x1.y, x1.z, x1.w};
#pragma unroll
        for (int i = 0; i < 8; i++) {
            unsigned long long av2 = pk2(av[i], av[i]);
            unsigned long long xv2 = pk2(xv[i], xv[i]);
            fma2(acc01[i], av2, wl.x);
            fma2(acc01[i], xv2, wr.x);
            fma2(acc23[i], av2, wl.y);
            fma2(acc23[i], xv2, wr.y);
        }
    }

    float4 bb = *reinterpret_cast<const float4*>(&sB[4 * jg]);
#pragma unroll
    for (int i = 0; i < 8; i++) {
        int node = node0 + nbase + i;
        if (node < N_NODES) {
            float2 p01 = up2(acc01[i]);
            float2 p23 = up2(acc23[i]);
            float4 r;
            r.x = fmaxf(p01.x + bb.x, 0.f);
            r.y = fmaxf(p01.y + bb.y, 0.f);
            r.z = fmaxf(p23.x + bb.z, 0.f);
            r.w = fmaxf(p23.y + bb.w, 0.f);
            *reinterpret_cast<float4*>(&g_h1[(long)node * HID + 4 * jg]) = r;
        }
    }
}

// ---------------------------------------------------------------------------
// Dense layer 2 (register-blocked, f32x2): z = h1@W2_l ; o = h1@W2_r + b2
// ---------------------------------------------------------------------------
#define D2_TILE    128
#define D2_THREADS 192
#define HT_STRIDE  132
#define D2_SMEM_FLOATS (HID*OSTRIDE*2 + OSTRIDE + HID*HT_STRIDE)

__global__ void __launch_bounds__(D2_THREADS)
k_dense2(const float* __restrict__ W2l,
         const float* __restrict__ W2r,
         const float* __restrict__ b2) {
    extern __shared__ float sm2[];
    float* sWl = sm2;
    float* sWr = sWl + HID * OSTRIDE;
    float* sB  = sWr + HID * OSTRIDE;
    float* sHT = sB + OSTRIDE;

    int tid = threadIdx.x;
    int node0 = blockIdx.x * D2_TILE;

    for (int i = tid; i < HID * OSTRIDE; i += D2_THREADS) {
        int k = i / OSTRIDE;
        int c = i - k * OSTRIDE;
        sWl[i] = (c < NC) ? W2l[k * NC + c] : 0.f;
        sWr[i] = (c < NC) ? W2r[k * NC + c] : 0.f;
    }
    if (tid < OSTRIDE) sB[tid] = (tid < NC) ? b2[tid] : 0.f;

    for (int i = tid; i < D2_TILE * 16; i += D2_THREADS) {
        int n  = i >> 4;
        int kg = i & 15;
        int node = node0 + n;
        float4 v = make_float4(0.f, 0.f, 0.f, 0.f);
        if (node < N_NODES)
            v = *reinterpret_cast<const float4*>(
                &g_h1[(long)node * HID + 4 * kg]);
        sHT[(4 * kg + 0) * HT_STRIDE + n] = v.x;
        sHT[(4 * kg + 1) * HT_STRIDE + n] = v.y;
        sHT[(4 * kg + 2) * HT_STRIDE + n] = v.z;
        sHT[(4 * kg + 3) * HT_STRIDE + n] = v.w;
    }
    __syncthreads();

    int st = tid / 48;
    int r  = tid - st * 48;
    int ms = r / 12;
    int jg = r - ms * 12;
    int nbase = st * 32 + ms * 8;

    unsigned long long az01[8], az23[8], ao01[8], ao23[8];
#pragma unroll
    for (int i = 0; i < 8; i++) {
        az01[i] = 0ULL; az23[i] = 0ULL; ao01[i] = 0ULL; ao23[i] = 0ULL;
    }

#pragma unroll 4
    for (int k = 0; k < HID; k++) {
        ulonglong2 wl = *reinterpret_cast<const ulonglong2*>(&sWl[k * OSTRIDE + 4 * jg]);
        ulonglong2 wr = *reinterpret_cast<const ulonglong2*>(&sWr[k * OSTRIDE + 4 * jg]);
        float4 h0  = *reinterpret_cast<const float4*>(&sHT[k * HT_STRIDE + nbase]);
        float4 h1v = *reinterpret_cast<const float4*>(&sHT[k * HT_STRIDE + nbase + 4]);
        float hv[8] = {h0.x, h0.y, h0.z, h0.w, h1v.x, h1v.y, h1v.z, h1v.w};
#pragma unroll
        for (int i = 0; i < 8; i++) {
            unsigned long long h2 = pk2(hv[i], hv[i]);
            fma2(az01[i], h2, wl.x);
            fma2(az23[i], h2, wl.y);
            fma2(ao01[i], h2, wr.x);
            fma2(ao23[i], h2, wr.y);
        }
    }

    float4 bb = *reinterpret_cast<const float4*>(&sB[4 * jg]);
#pragma unroll
    for (int i = 0; i < 8; i++) {
        int node = node0 + nbase + i;
        if (node < N_NODES) {
            long off = (long)node * OSTRIDE + 4 * jg;
            float2 z01 = up2(az01[i]);
            float2 z23 = up2(az23[i]);
            float4 z = make_float4(z01.x, z01.y, z23.x, z23.y);
            *reinterpret_cast<float4*>(&g_z[off]) = z;
            float2 o01 = up2(ao01[i]);
            float2 o23 = up2(ao23[i]);
            float4 o;
            o.x = o01.x + bb.x; o.y = o01.y + bb.y;
            o.z = o23.x + bb.z; o.w = o23.y + bb.w;
            *reinterpret_cast<float4*>(&g_o[off]) = o;
        }
    }
}

// ---------------------------------------------------------------------------
// Layer-2 aggregation + log_softmax fused (gather, warp per node, pipelined)
// ---------------------------------------------------------------------------
__global__ void __launch_bounds__(256) k_agg2_softmax(float* __restrict__ out) {
    int warp = (blockIdx.x * blockDim.x + threadIdx.x) >> 5;
    int lane = threadIdx.x & 31;
    if (warp >= N_NODES) return;
    int n = warp;

    const float* orow = &g_o[(long)n * OSTRIDE];
    float o0 = orow[lane];
    float o1 = (lane < NC - 32) ? orow[32 + lane] : 0.f;

    int beg = g_off[n];
    int end = g_off[n + 1];
    int e = beg;
    int sA = (e     < end) ? __ldg(&g_ssrc[e])     : 0;
    int sB = (e + 1 < end) ? __ldg(&g_ssrc[e + 1]) : 0;
    while (e < end) {
        int s0 = sA, s1 = sB;
        float m1 = (e + 1 < end) ? 1.f : 0.f;
        sA = (e + 2 < end) ? __ldg(&g_ssrc[e + 2]) : 0;
        sB = (e + 3 < end) ? __ldg(&g_ssrc[e + 3]) : 0;
        const float* z0 = &g_z[(long)s0 * OSTRIDE];
        const float* z1 = &g_z[(long)s1 * OSTRIDE];
        float v00 = __ldg(&z0[lane]);
        float v10 = __ldg(&z1[lane]);
        o0 += v00 + m1 * v10;
        if (lane < NC - 32) {
            float v01 = __ldg(&z0[32 + lane]);
            float v11 = __ldg(&z1[32 + lane]);
            o1 += v01 + m1 * v11;
        }
        e += 2;
    }

    float mx = fmaxf(o0, (lane < NC - 32) ? o1 : -INFINITY);
#pragma unroll
    for (int off = 16; off > 0; off >>= 1)
        mx = fmaxf(mx, __shfl_xor_sync(0xFFFFFFFFu, mx, off));

    float sum = expf(o0 - mx) + ((lane < NC - 32) ? expf(o1 - mx) : 0.f);
#pragma unroll
    for (int off = 16; off > 0; off >>= 1)
        sum += __shfl_xor_sync(0xFFFFFFFFu, sum, off);

    float lse = mx + logf(sum);
    out[(long)n * NC + lane] = o0 - lse;
    if (lane < NC - 32)
        out[(long)n * NC + 32 + lane] = o1 - lse;
}

// ---------------------------------------------------------------------------
extern "C" void kernel_launch(void* const* d_in, const int* in_sizes, int n_in,
                              void* d_out, int out_size) {
    const float* x   = (const float*)d_in[0];
    const float* W1l = (const float*)d_in[1];
    const float* W1r = (const float*)d_in[2];
    const float* b1  = (const float*)d_in[3];
    const float* W2l = (const float*)d_in[4];
    const float* W2r = (const float*)d_in[5];
    const float* b2  = (const float*)d_in[6];
    const int*   src = (const int*)d_in[7];
    const int*   dst = (const int*)d_in[8];
    float* out = (float*)d_out;

    (void)in_sizes; (void)n_in; (void)out_size;

    const int d1_smem = D1_SMEM_FLOATS * 4;
    const int d2_smem = D2_SMEM_FLOATS * 4;
    cudaFuncSetAttribute(k_dense1, cudaFuncAttributeMaxDynamicSharedMemorySize,
                         d1_smem);
    cudaFuncSetAttribute(k_dense2, cudaFuncAttributeMaxDynamicSharedMemorySize,
                         d2_smem);

    // --- CSR build ---
    k_zero_cnt<<<(SCAN_NB * SCAN_B + 255) / 256, 256>>>();
    k_hist<<<1480, 256>>>(dst);
    k_scan_block<<<SCAN_NB, SCAN_B>>>();
    k_scan_top<<<1, 128>>>();
    k_scan_add<<<SCAN_NB, SCAN_B>>>();
    k_bucket<<<1480, 256>>>(src, dst);

    // --- Layer 1 ---
    k_agg1<<<(N_NODES + 7) / 8, 256>>>(x);
    k_dense1<<<(N_NODES + D1_TILE - 1) / D1_TILE, D1_THREADS, d1_smem>>>(
        x, W1l, W1r, b1);

    // --- Layer 2 ---
    k_dense2<<<(N_NODES + D2_TILE - 1) / D2_TILE, D2_THREADS, d2_smem>>>(
        W2l, W2r, b2);
    k_agg2_softmax<<<(N_NODES + 7) / 8, 256>>>(out);
}